// round 1
// baseline (speedup 1.0000x reference)
#include <cuda_runtime.h>
#include <cstdint>
#include <cstddef>

#define NMAX   500000
#define GQ     128
#define GCELLS (2*GQ*GQ*GQ)
#define KTOP   256
#define NBINS  4096
#define CANDMAX 4096

// ------------------------- scratch (__device__ globals, no allocs) ---------
__device__ int                 g_grid[GCELLS];
__device__ int                 g_owner[NMAX];
__device__ unsigned char       g_peak[NMAX];
__device__ int                 g_hist[NBINS];
__device__ int                 g_thresh;
__device__ int                 g_candcnt;
__device__ int                 g_touchcnt;
__device__ unsigned long long  g_ckey[CANDMAX];
__device__ float               g_conf[KTOP];
__device__ int                 g_topidx[KTOP];
__device__ int                 g_touched[2048];
__device__ float               g_sums[KTOP*128];
__device__ float               g_counts[KTOP];
__device__ float               g_cols[257*32];

// ------------------------- clear ------------------------------------------
__global__ void k_clear(int n)
{
    int i = blockIdx.x * blockDim.x + threadIdx.x;
    if (i < GCELLS) g_grid[i] = -1;
    if (i < NMAX)   g_owner[i] = -1;
    if (i < NBINS)  g_hist[i]  = 0;
    if (i < KTOP*128) g_sums[i] = 0.0f;
    if (i < KTOP)   g_counts[i] = 0.0f;
    if (i == 0) { g_candcnt = 0; g_touchcnt = 0; }
}

// ------------------------- fill grid --------------------------------------
__global__ void k_fill(const int* __restrict__ coords, int n)
{
    int i = blockIdx.x * blockDim.x + threadIdx.x;
    if (i >= n) return;
    int4 c = ((const int4*)coords)[i];
    int cell = ((c.x * GQ + c.y) * GQ + c.z) * GQ + c.w;
    g_grid[cell] = i;
}

// ------------------------- peak detection + histogram ---------------------
__global__ void k_peaks(const int* __restrict__ coords,
                        const float* __restrict__ scores, int n)
{
    int i = blockIdx.x * blockDim.x + threadIdx.x;
    if (i >= n) return;
    float s = scores[i];
    bool pk = false;
    if (s > 0.1f) {
        float nm = -1e30f;
        int4 c = ((const int4*)coords)[i];
        const int dx[7] = {0, 1,-1, 0, 0, 0, 0};
        const int dy[7] = {0, 0, 0, 1,-1, 0, 0};
        const int dz[7] = {0, 0, 0, 0, 0, 1,-1};
        #pragma unroll
        for (int o = 0; o < 7; ++o) {
            int nx = c.y + dx[o], ny = c.z + dy[o], nz = c.w + dz[o];
            if (nx < 0 || nx >= GQ || ny < 0 || ny >= GQ || nz < 0 || nz >= GQ) continue;
            int cell = ((c.x * GQ + nx) * GQ + ny) * GQ + nz;
            int j = g_grid[cell];
            if (j >= 0) {
                float sj = scores[j];
                if (sj > 0.1f) nm = fmaxf(nm, sj);
            }
        }
        pk = (s >= nm - 1e-6f) && (s >= 0.5f);
    }
    g_peak[i] = pk ? 1 : 0;
    if (pk) {
        int b = (int)((s - 0.5f) * 8192.0f);
        b = b < 0 ? 0 : (b > NBINS-1 ? NBINS-1 : b);
        atomicAdd(&g_hist[b], 1);
    }
}

// ------------------------- threshold scan (1 block, 256 thr) --------------
__global__ void k_scan()
{
    __shared__ int h[NBINS];
    __shared__ int sup[64];
    int t = threadIdx.x;
    for (int i = t; i < NBINS; i += 256) h[i] = g_hist[i];
    __syncthreads();
    if (t < 64) {
        int s = 0;
        for (int m = 0; m < 64; ++m) s += h[t*64 + m];
        sup[t] = s;
    }
    __syncthreads();
    if (t == 0) {
        int total = 0;
        for (int s = 0; s < 64; ++s) total += sup[s];
        int target = total < KTOP ? total : KTOP;
        int T = 0;
        if (target > 0) {
            int acc = 0, sb = 63;
            for (; sb >= 0; --sb) {
                if (acc + sup[sb] >= target) break;
                acc += sup[sb];
            }
            for (int b = 63; b >= 0; --b) {
                acc += h[sb*64 + b];
                if (acc >= target) { T = sb*64 + b; break; }
            }
        }
        g_thresh = T;
    }
}

// ------------------------- collect candidates -----------------------------
__global__ void k_collect(const float* __restrict__ scores, int n)
{
    int i = blockIdx.x * blockDim.x + threadIdx.x;
    if (i >= n || !g_peak[i]) return;
    float s = scores[i];
    int b = (int)((s - 0.5f) * 8192.0f);
    b = b < 0 ? 0 : (b > NBINS-1 ? NBINS-1 : b);
    if (b >= g_thresh) {
        int pos = atomicAdd(&g_candcnt, 1);
        if (pos < CANDMAX) {
            unsigned long long key =
                ((unsigned long long)__float_as_uint(s) << 32)
              | (unsigned long long)(0xFFFFFFFFu - (unsigned)i);
            g_ckey[pos] = key;
        }
    }
}

// ------------------------- bitonic top-256 (1 block, 1024 thr) ------------
__global__ void k_sort(float* conf_out)
{
    __shared__ unsigned long long sk[CANDMAX];
    int t = threadIdx.x;
    int cnt = g_candcnt;
    if (cnt > CANDMAX) cnt = CANDMAX;
    for (int i = t; i < CANDMAX; i += 1024)
        sk[i] = (i < cnt) ? g_ckey[i] : 0ULL;
    __syncthreads();
    for (int k = 2; k <= CANDMAX; k <<= 1) {
        for (int j = k >> 1; j > 0; j >>= 1) {
            for (int i = t; i < CANDMAX; i += 1024) {
                int ixj = i ^ j;
                if (ixj > i) {
                    unsigned long long a = sk[i], b = sk[ixj];
                    bool sw = ((i & k) == 0) ? (a < b) : (a > b);
                    if (sw) { sk[i] = b; sk[ixj] = a; }
                }
            }
            __syncthreads();
        }
    }
    if (t < KTOP) {
        bool valid = t < cnt;
        unsigned long long key = sk[t];
        float sc = valid ? __uint_as_float((unsigned)(key >> 32)) : 0.0f;
        g_conf[t] = sc;
        g_topidx[t] = valid ? (int)(0xFFFFFFFFu - (unsigned)(key & 0xFFFFFFFFULL)) : -1;
        if (conf_out) conf_out[t] = sc;
    }
}

// ------------------------- owner assignment (1 block, 256 thr) ------------
__global__ void k_owner(const int* __restrict__ coords,
                        const float* __restrict__ scores)
{
    int k = threadIdx.x;
    if (k >= KTOP) return;
    int p = g_topidx[k];
    if (p < 0) return;
    int4 c = ((const int4*)coords)[p];
    const int dx[7] = {0, 1,-1, 0, 0, 0, 0};
    const int dy[7] = {0, 0, 0, 1,-1, 0, 0};
    const int dz[7] = {0, 0, 0, 0, 0, 1,-1};
    #pragma unroll
    for (int o = 0; o < 7; ++o) {
        int nx = c.y + dx[o], ny = c.z + dy[o], nz = c.w + dz[o];
        if (nx < 0 || nx >= GQ || ny < 0 || ny >= GQ || nz < 0 || nz >= GQ) continue;
        int cell = ((c.x * GQ + nx) * GQ + ny) * GQ + nz;
        int j = g_grid[cell];
        if (j >= 0 && scores[j] > 0.1f) {
            int old = atomicMax(&g_owner[j], k);
            if (old == -1) {
                int pos = atomicAdd(&g_touchcnt, 1);
                g_touched[pos] = j;
            }
        }
    }
}

// ------------------------- segment sums (1792 blocks x 128) ---------------
__global__ void k_segsum(const float* __restrict__ feats)
{
    if ((int)blockIdx.x >= g_touchcnt) return;
    int i = g_touched[blockIdx.x];
    int o = g_owner[i];
    atomicAdd(&g_sums[o*128 + threadIdx.x], feats[(size_t)i*128 + threadIdx.x]);
    if (threadIdx.x == 0) atomicAdd(&g_counts[o], 1.0f);
}

// ------------------------- build cols (257 blocks x 128) ------------------
__global__ void k_cols(const float* __restrict__ Wc,
                       const float* __restrict__ bc,
                       const float* __restrict__ bg)
{
    int k = blockIdx.x;
    int t = threadIdx.x;
    if (k == 0) {
        if (t < 32) g_cols[t] = bg[t];
        return;
    }
    int seg = k - 1;
    __shared__ float mean[128];
    float cnt = fmaxf(g_counts[seg], 1.0f);
    mean[t] = g_sums[seg*128 + t] / cnt;
    __syncthreads();
    if (t < 32) {
        float a = bc[t];
        #pragma unroll 8
        for (int m = 0; m < 128; ++m) a += mean[m] * Wc[m*32 + t];
        g_cols[k*32 + t] = g_conf[seg] * a;
    }
}

// ------------------------- fused dense GEMM -------------------------------
// desc = feats@Wv + bv (N x 32), out = desc @ cols^T (N x 257)
// smem floats: A_T 64x132 = 8448 | Wv 128x36 = 4608 | descT 32x132 = 4224 |
//              colsT 32x260 = 8320 | bv 32  => 25632 floats = 102528 B
#define SM_A    0
#define SM_WV   8448
#define SM_D    13056
#define SM_C    17280
#define SM_BV   25600
#define SM_FLTS 25632

__global__ void __launch_bounds__(256, 2)
k_main(const float* __restrict__ A, const float* __restrict__ Wv,
       const float* __restrict__ bv, float* __restrict__ outI, int n)
{
    extern __shared__ float sm[];
    float* sA  = sm + SM_A;
    float* sWv = sm + SM_WV;
    float* sD  = sm + SM_D;
    float* sC  = sm + SM_C;
    float* sbv = sm + SM_BV;

    int t = threadIdx.x;
    int row0 = blockIdx.x * 128;
    int rg = t >> 3;     // 0..31 -> rows 4rg..4rg+3
    int dg = t & 7;      // 0..7  -> stage1 d 4dg..4dg+3 / stage2 cols 4dg..

    // preload Wv (k-major padded 36), colsT (d-major padded 260), bv
    for (int i = t; i < 4096; i += 256) {
        int k = i >> 5, d = i & 31;
        sWv[k*36 + d] = Wv[i];
    }
    for (int i = t; i < 257*32; i += 256) {
        int c = i >> 5, d = i & 31;
        sC[d*260 + c] = g_cols[i];
    }
    if (t < 32) sbv[t] = bv[t];

    // ---------------- stage 1: desc = A @ Wv + bv ----------------
    float acc[4][4];
    #pragma unroll
    for (int j = 0; j < 4; ++j)
        #pragma unroll
        for (int jj = 0; jj < 4; ++jj) acc[j][jj] = 0.0f;

    for (int sl = 0; sl < 2; ++sl) {
        __syncthreads();
        // load 128 rows x 64 k slice, transposed into sA[k][r] (stride 132)
        #pragma unroll
        for (int it = 0; it < 8; ++it) {
            int idx = t + 256*it;        // float4 unit id, 0..2047
            int r = idx >> 4, q = idx & 15;
            int grow = row0 + r;
            float4 v = make_float4(0.f, 0.f, 0.f, 0.f);
            if (grow < n)
                v = *(const float4*)(A + (size_t)grow*128 + sl*64 + 4*q);
            sA[(4*q+0)*132 + r] = v.x;
            sA[(4*q+1)*132 + r] = v.y;
            sA[(4*q+2)*132 + r] = v.z;
            sA[(4*q+3)*132 + r] = v.w;
        }
        __syncthreads();
        #pragma unroll 8
        for (int kk = 0; kk < 64; ++kk) {
            int k = sl*64 + kk;
            float4 av = *(const float4*)(sA  + kk*132 + 4*rg);
            float4 wv = *(const float4*)(sWv + k*36  + 4*dg);
            acc[0][0] += av.x*wv.x; acc[0][1] += av.x*wv.y; acc[0][2] += av.x*wv.z; acc[0][3] += av.x*wv.w;
            acc[1][0] += av.y*wv.x; acc[1][1] += av.y*wv.y; acc[1][2] += av.y*wv.z; acc[1][3] += av.y*wv.w;
            acc[2][0] += av.z*wv.x; acc[2][1] += av.z*wv.y; acc[2][2] += av.z*wv.z; acc[2][3] += av.z*wv.w;
            acc[3][0] += av.w*wv.x; acc[3][1] += av.w*wv.y; acc[3][2] += av.w*wv.z; acc[3][3] += av.w*wv.w;
        }
    }
    // write descT[d][r] (stride 132), add bv
    #pragma unroll
    for (int jj = 0; jj < 4; ++jj) {
        float b = sbv[4*dg + jj];
        #pragma unroll
        for (int j = 0; j < 4; ++j)
            sD[(4*dg + jj)*132 + 4*rg + j] = acc[j][jj] + b;
    }
    __syncthreads();

    // ---------------- stage 2: out = desc @ cols^T ----------------
    int cg = dg;
    for (int cb = 0; cb < 256; cb += 32) {
        float o[4][4];
        #pragma unroll
        for (int j = 0; j < 4; ++j)
            #pragma unroll
            for (int jj = 0; jj < 4; ++jj) o[j][jj] = 0.0f;
        #pragma unroll 8
        for (int k = 0; k < 32; ++k) {
            float4 dv = *(const float4*)(sD + k*132 + 4*rg);
            float4 wv = *(const float4*)(sC + k*260 + cb + 4*cg);
            o[0][0] += dv.x*wv.x; o[0][1] += dv.x*wv.y; o[0][2] += dv.x*wv.z; o[0][3] += dv.x*wv.w;
            o[1][0] += dv.y*wv.x; o[1][1] += dv.y*wv.y; o[1][2] += dv.y*wv.z; o[1][3] += dv.y*wv.w;
            o[2][0] += dv.z*wv.x; o[2][1] += dv.z*wv.y; o[2][2] += dv.z*wv.z; o[2][3] += dv.z*wv.w;
            o[3][0] += dv.w*wv.x; o[3][1] += dv.w*wv.y; o[3][2] += dv.w*wv.z; o[3][3] += dv.w*wv.w;
        }
        #pragma unroll
        for (int j = 0; j < 4; ++j) {
            int grow = row0 + 4*rg + j;
            if (grow < n) {
                float* op = outI + (size_t)grow*257 + cb + 4*cg;
                op[0] = o[j][0]; op[1] = o[j][1]; op[2] = o[j][2]; op[3] = o[j][3];
            }
        }
    }
    // last column (c = 256)
    if (t < 128) {
        int r = t;
        float a = 0.0f;
        #pragma unroll 8
        for (int k = 0; k < 32; ++k)
            a += sD[k*132 + r] * sC[k*260 + 256];
        int grow = row0 + r;
        if (grow < n) outI[(size_t)grow*257 + 256] = a;
    }
}

// ------------------------- launch -----------------------------------------
extern "C" void kernel_launch(void* const* d_in, const int* in_sizes, int n_in,
                              void* d_out, int out_size)
{
    const int*   coords = (const int*)  d_in[0];
    const float* feats  = (const float*)d_in[1];
    const float* scores = (const float*)d_in[2];
    const float* Wv     = (const float*)d_in[3];
    const float* bv     = (const float*)d_in[4];
    const float* Wc     = (const float*)d_in[5];
    const float* bc     = (const float*)d_in[6];
    const float* bg     = (const float*)d_in[7];

    int n = in_sizes[0] / 4;
    if (n > NMAX) n = NMAX;

    float* out = (float*)d_out;
    long long inst = (long long)n * 257;
    int off = (int)((long long)out_size - inst);   // expect 256 (conf first)
    if (off < 0) off = 0;
    float* conf_out = (off >= KTOP) ? out : nullptr;
    float* inst_out = out + off;

    cudaFuncSetAttribute(k_main, cudaFuncAttributeMaxDynamicSharedMemorySize,
                         SM_FLTS * (int)sizeof(float));

    int nb = (n + 255) / 256;
    k_clear <<<(GCELLS + 255) / 256, 256>>>(n);
    k_fill  <<<nb, 256>>>(coords, n);
    k_peaks <<<nb, 256>>>(coords, scores, n);
    k_scan  <<<1, 256>>>();
    k_collect<<<nb, 256>>>(scores, n);
    k_sort  <<<1, 1024>>>(conf_out);
    k_owner <<<1, 256>>>(coords, scores);
    k_segsum<<<1792, 128>>>(feats);
    k_cols  <<<257, 128>>>(Wc, bc, bg);

    int mb = (n + 127) / 128;
    k_main<<<mb, 256, SM_FLTS * (int)sizeof(float)>>>(feats, Wv, bv, inst_out, n);
}